// round 2
// baseline (speedup 1.0000x reference)
#include <cuda_runtime.h>

#define BB 8
#define CC 19
#define HH 384
#define WW 384
#define HW (HH*WW)
#define NPIX (BB*HW)
#define NBLK (NPIX/256)
#define DBOUND 777   /* B+C+H+W, the reference's init value */

__device__ double g_ce;
__device__ unsigned long long g_bd;
__device__ unsigned char g_pred[NPIX];
__device__ unsigned char g_tgt[NPIX];
__device__ unsigned char g_tb[NPIX];
__device__ short g_vd[NPIX];

__global__ void k_init() { g_ce = 0.0; g_bd = 0ull; }

// CE (sum, ignore 255) + argmax pred + compress targets to u8
__global__ __launch_bounds__(256) void k_ce_pred(const float* __restrict__ x,
                                                 const int* __restrict__ t) {
    int p = blockIdx.x * 256 + threadIdx.x;
    int b = p / HW, hw = p - b * HW;
    const float* xp = x + (size_t)b * (CC * HW) + hw;
    float v[CC];
#pragma unroll
    for (int c = 0; c < CC; c++) v[c] = xp[(size_t)c * HW];
    float m = v[0]; int arg = 0;
#pragma unroll
    for (int c = 1; c < CC; c++) if (v[c] > m) { m = v[c]; arg = c; }
    float s = 0.f;
#pragma unroll
    for (int c = 0; c < CC; c++) s += __expf(v[c] - m);
    int tgt = t[p];
    float nll = 0.f;
    if (tgt != 255) {
        float vt = v[0];
#pragma unroll
        for (int c = 1; c < CC; c++) vt = (c == tgt) ? v[c] : vt;
        nll = m + __logf(s) - vt;
    }
    g_pred[p] = (unsigned char)arg;
    g_tgt[p]  = (unsigned char)tgt;

    float r = nll;
#pragma unroll
    for (int o = 16; o; o >>= 1) r += __shfl_down_sync(0xffffffffu, r, o);
    __shared__ float ws[8];
    if ((threadIdx.x & 31) == 0) ws[threadIdx.x >> 5] = r;
    __syncthreads();
    if (threadIdx.x == 0) {
        float s2 = 0.f;
#pragma unroll
        for (int i = 0; i < 8; i++) s2 += ws[i];
        atomicAdd(&g_ce, (double)s2);
    }
}

// target border map: (forward-diff down + forward-diff right) != 0, zero-padded at ends
__global__ __launch_bounds__(256) void k_tborder() {
    int p = blockIdx.x * 256 + threadIdx.x;
    int hw = p % HW; int y = hw / WW; int xx = hw - y * WW;
    int t0 = g_tgt[p];
    int d = 0;
    if (y  < HH - 1) d += (int)g_tgt[p + WW] - t0;
    if (xx < WW - 1) d += (int)g_tgt[p + 1]  - t0;
    g_tb[p] = (unsigned char)(d != 0);
}

// vertical 1D border distance per pixel (expanding search, exact, capped at DBOUND)
__global__ __launch_bounds__(256) void k_vert() {
    int p = blockIdx.x * 256 + threadIdx.x;
    int b = p / HW, hw = p - b * HW;
    int y = hw / WW; int xx = hw - y * WW;
    const unsigned char* col = g_tb + b * HW + xx;
    int best = DBOUND;
    for (int k = 0; k < best; k++) {
        int yu = y - k, yd = y + k;
        bool inb = false;
        if (yu >= 0)           { inb = true; if (col[yu * WW]) { best = k; break; } }
        if (yd < HH && k != 0) { inb = true; if (col[yd * WW]) { best = k; break; } }
        if (!inb) break;
    }
    g_vd[p] = (short)best;
}

// pred border + horizontal combine: dist = min_k max(k, g[x±k]); sum over pred-border px
__global__ __launch_bounds__(256) void k_hdist() {
    int p = blockIdx.x * 256 + threadIdx.x;
    int b = p / HW, hw = p - b * HW;
    int y = hw / WW; int xx = hw - y * WW;
    int pr = g_pred[p];
    int d = 0;
    if (y  < HH - 1) d += (int)g_pred[p + WW] - pr;
    if (xx < WW - 1) d += (int)g_pred[p + 1]  - pr;
    int dist = 0;
    if (d != 0) {
        const short* gr = g_vd + b * HW + y * WW;
        int best = gr[xx];
        for (int k = 1; k < best; k++) {
            bool inb = false;
            int xl = xx - k, xr = xx + k;
            if (xl >= 0) { inb = true; int c = (int)gr[xl]; c = c > k ? c : k; if (c < best) best = c; }
            if (xr < WW) { inb = true; int c = (int)gr[xr]; c = c > k ? c : k; if (c < best) best = c; }
            if (!inb) break;
        }
        dist = best;
    }
    int r = dist;
#pragma unroll
    for (int o = 16; o; o >>= 1) r += __shfl_down_sync(0xffffffffu, r, o);
    __shared__ int ws[8];
    if ((threadIdx.x & 31) == 0) ws[threadIdx.x >> 5] = r;
    __syncthreads();
    if (threadIdx.x == 0) {
        int s2 = 0;
#pragma unroll
        for (int i = 0; i < 8; i++) s2 += ws[i];
        atomicAdd(&g_bd, (unsigned long long)s2);
    }
}

__global__ void k_final(float* out) {
    out[0] = (float)(g_ce + 0.2 * (double)g_bd);
}

extern "C" void kernel_launch(void* const* d_in, const int* in_sizes, int n_in,
                              void* d_out, int out_size) {
    const float* slices = (const float*)d_in[0];
    const int* targets = (const int*)d_in[1];
    float* out = (float*)d_out;
    k_init<<<1, 1>>>();
    k_ce_pred<<<NBLK, 256>>>(slices, targets);
    k_tborder<<<NBLK, 256>>>();
    k_vert<<<NBLK, 256>>>();
    k_hdist<<<NBLK, 256>>>();
    k_final<<<1, 1>>>(out);
}